// round 7
// baseline (speedup 1.0000x reference)
#include <cuda_runtime.h>
#include <cstdint>

// Shapes: N=100000, D=64, H=128, E=1600000
#define Dk     64
#define Hk     128
#define TE     128      // edges per tile
#define UVP    136      // Us/Vs pitch (floats) -> conflict-free f2 fragment loads
#define W2P    136
#define UVPc   132
#define MAXN   100000

// Scratch: U = nodes @ W1[:64,:] (columns permuted), V = nodes @ W1[64:,:]
__device__ float g_U[(size_t)MAXN * Hk];
__device__ float g_V[(size_t)MAXN * Hk];

// hidden-dim permutation within each 8-group: position s holds unit perm[s]
__device__ __constant__ int c_perm[8] = {0, 4, 1, 5, 2, 6, 3, 7};

// ---------------- smem float-index layout for edge kernel ----------------
#define F_US   0                          // [128][UVP]
#define F_VS   (F_US + TE * UVP)          // [128][UVP]
#define F_W2   (F_VS + TE * UVP)          // [64][W2P]
#define F_B1   (F_W2 + Dk * W2P)          // 128 (permuted)
#define F_B2   (F_B1 + Hk)                // 64
#define F_EIS  (F_B2 + Dk)                // 128 ints
#define F_EJS  (F_EIS + TE)
#define F_TOT  (F_EJS + TE)
#define EDGE_SMEM_BYTES (F_TOT * 4)

extern __shared__ char smem_raw[];

__device__ __forceinline__ uint32_t smem_u32(const void* p) {
    uint32_t a;
    asm("{ .reg .u64 t; cvta.to.shared.u64 t, %1; cvt.u32.u64 %0, t; }" : "=r"(a) : "l"(p));
    return a;
}
__device__ __forceinline__ float to_tf32(float x) {
    float y; asm("cvt.rna.tf32.f32 %0, %1;" : "=f"(y) : "f"(x)); return y;
}
__device__ __forceinline__ void red_add_v2(float* addr, float x, float y) {
    asm volatile("red.global.add.v2.f32 [%0], {%1,%2};"
                 :: "l"(addr), "f"(x), "f"(y) : "memory");
}
__device__ __forceinline__ void cp_async16(void* sdst, const void* gsrc) {
    uint32_t s = smem_u32(sdst);
    asm volatile("cp.async.cg.shared.global [%0], [%1], 16;" :: "r"(s), "l"(gsrc) : "memory");
}
__device__ __forceinline__ void mma_tf32(float c[4],
                                         uint32_t a0, uint32_t a1, uint32_t a2, uint32_t a3,
                                         uint32_t b0, uint32_t b1) {
    asm volatile(
        "mma.sync.aligned.m16n8k8.row.col.f32.tf32.tf32.f32 "
        "{%0,%1,%2,%3}, {%4,%5,%6,%7}, {%8,%9}, {%0,%1,%2,%3};"
        : "+f"(c[0]), "+f"(c[1]), "+f"(c[2]), "+f"(c[3])
        : "r"(a0), "r"(a1), "r"(a2), "r"(a3), "r"(b0), "r"(b1));
}

// ---------------- Kernel 0: out = nodes ----------------
__global__ __launch_bounds__(256) void copy_kernel(const float* __restrict__ nodes,
                                                   float* __restrict__ out, int n4) {
    int i = blockIdx.x * blockDim.x + threadIdx.x;
    if (i < n4) ((float4*)out)[i] = ((const float4*)nodes)[i];
}

// ---------------- Kernel A: U/V precompute (fp32 SIMT, permuted columns) ----
__global__ __launch_bounds__(256) void uv_kernel(const float* __restrict__ nodes,
                                                 const float* __restrict__ W1, int N) {
    float* smem = (float*)smem_raw;
    float* Ns  = smem;                // [64][UVPc]
    float* W1s = smem + 64 * UVPc;    // [128][128] (columns permuted)

    int tid = threadIdx.x;
    for (int idx = tid; idx < 128 * 128; idx += 256) {
        int c = idx & 127;
        int src_c = (c & ~7) + c_perm[c & 7];
        W1s[idx] = W1[(idx & ~127) + src_c];
    }

    int n_base = blockIdx.x * 128;
    for (int idx = tid; idx < 128 * 64; idx += 256) {
        int k = idx & 63, n = idx >> 6;
        int gn = n_base + n;
        Ns[k * UVPc + n] = (gn < N) ? nodes[gn * Dk + k] : 0.f;
    }
    __syncthreads();

    int ty = tid >> 4, tx = tid & 15;
    int n0 = ty * 8, c0 = tx * 8;

    #pragma unroll
    for (int pass = 0; pass < 2; pass++) {
        const float* Wb = W1s + pass * 64 * 128;
        float acc[8][8];
        #pragma unroll
        for (int a = 0; a < 8; a++)
            #pragma unroll
            for (int b = 0; b < 8; b++) acc[a][b] = 0.f;

        #pragma unroll 4
        for (int k = 0; k < 64; k++) {
            float4 a0 = *(const float4*)&Ns[k * UVPc + n0];
            float4 a1 = *(const float4*)&Ns[k * UVPc + n0 + 4];
            float4 w0 = *(const float4*)&Wb[k * 128 + c0];
            float4 w1 = *(const float4*)&Wb[k * 128 + c0 + 4];
            float af[8] = {a0.x, a0.y, a0.z, a0.w, a1.x, a1.y, a1.z, a1.w};
            float wf[8] = {w0.x, w0.y, w0.z, w0.w, w1.x, w1.y, w1.z, w1.w};
            #pragma unroll
            for (int a = 0; a < 8; a++)
                #pragma unroll
                for (int b = 0; b < 8; b++) acc[a][b] += af[a] * wf[b];
        }

        float* Out = pass ? g_V : g_U;
        #pragma unroll
        for (int a = 0; a < 8; a++) {
            int gn = n_base + n0 + a;
            if (gn < N) {
                *(float4*)&Out[(size_t)gn * Hk + c0] =
                    make_float4(acc[a][0], acc[a][1], acc[a][2], acc[a][3]);
                *(float4*)&Out[(size_t)gn * Hk + c0 + 4] =
                    make_float4(acc[a][4], acc[a][5], acc[a][6], acc[a][7]);
            }
        }
    }
}

// ---------------- Kernel B: persistent edge kernel ----------
// Per 128-edge tile, per direction:
//   cp.async-stage raw rows US = U[sn[e]], VS = V[on[e]]
//   A-fragments on the fly: a = tf32(relu(us + vs + b1))  (b1 register-resident)
//   C = H @ W2 via m16n8k8 tf32 mma  (warp = m32 x n32)
//   out[sn] += C + b2 via red.global.add.v2                (b2 register-resident)
__global__ __launch_bounds__(256, 1) void edge_kernel(const int* __restrict__ edges,
                                                      const float* __restrict__ W2,
                                                      const float* __restrict__ b1,
                                                      const float* __restrict__ b2,
                                                      float* __restrict__ out,
                                                      int E, int tiles) {
    float* smem = (float*)smem_raw;
    float* US  = smem + F_US;
    float* VS  = smem + F_VS;
    float* W2S = smem + F_W2;
    float* b1s = smem + F_B1;
    float* b2s = smem + F_B2;
    int*   eis = (int*)(smem + F_EIS);
    int*   ejs = (int*)(smem + F_EJS);

    int tid = threadIdx.x, wid = tid >> 5, lane = tid & 31;
    int rr = lane >> 2, q = lane & 3;

    // ---- one-time staging ----
    // W2S[n][k'] = tf32(W2[unit(k')][n])
    for (int idx = tid; idx < Hk * Dk; idx += 256) {
        int k = idx >> 6, n = idx & 63;
        int unit = (k & ~7) + c_perm[k & 7];
        W2S[n * W2P + k] = to_tf32(W2[unit * Dk + n]);
    }
    if (tid < Hk) b1s[tid] = b1[(tid & ~7) + c_perm[tid & 7]];
    if (tid < Dk) b2s[tid] = b2[tid];
    __syncthreads();

    // warp tiling: 4 m32-tiles x 2 n-halves
    int er0 = (wid & 3) * 32;
    int n0 = (wid >> 2) * 32;

    // register-resident bias fragments
    float2 b1r[16];
    #pragma unroll
    for (int g = 0; g < 16; g++) b1r[g] = *(const float2*)&b1s[g * 8 + 2 * q];
    float2 b2r[4];
    #pragma unroll
    for (int j = 0; j < 4; j++) b2r[j] = *(const float2*)&b2s[n0 + 8 * j + 2 * q];

    for (int t = blockIdx.x; t < tiles; t += gridDim.x) {
        int ebase = t * TE;
        if (tid < TE) {
            int e = ebase + tid;
            int a = 0, b = 0;
            if (e < E) { a = edges[2 * e]; b = edges[2 * e + 1]; }
            eis[tid] = a; ejs[tid] = b;
        }
        __syncthreads();

        #pragma unroll
        for (int dir = 0; dir < 2; dir++) {
            const int* sn = dir ? ejs : eis;    // U-index + scatter target
            const int* on = dir ? eis : ejs;    // V-index

            // ---- stage raw U/V rows via cp.async (512B per row) ----
            #pragma unroll 4
            for (int r = wid; r < TE; r += 8) {
                const float* up = g_U + (size_t)sn[r] * Hk;
                const float* vp = g_V + (size_t)on[r] * Hk;
                cp_async16(&US[r * UVP + lane * 4], up + lane * 4);
                cp_async16(&VS[r * UVP + lane * 4], vp + lane * 4);
            }
            asm volatile("cp.async.commit_group;" ::: "memory");
            asm volatile("cp.async.wait_group 0;" ::: "memory");
            __syncthreads();

            // ---- MMA with fused layer-1 in A-fragment loads ----
            float acc[2][4][4];
            #pragma unroll
            for (int mt = 0; mt < 2; mt++)
                #pragma unroll
                for (int j = 0; j < 4; j++)
                    #pragma unroll
                    for (int x = 0; x < 4; x++) acc[mt][j][x] = 0.f;

            #pragma unroll 4
            for (int g = 0; g < 16; g++) {
                int col = g * 8 + 2 * q;
                float2 bb = b1r[g];
                uint32_t a[2][4];
                #pragma unroll
                for (int mt = 0; mt < 2; mt++) {
                    int rbase = er0 + 16 * mt + rr;
                    float2 u0 = *(const float2*)&US[rbase * UVP + col];
                    float2 v0 = *(const float2*)&VS[rbase * UVP + col];
                    float2 u1 = *(const float2*)&US[(rbase + 8) * UVP + col];
                    float2 v1 = *(const float2*)&VS[(rbase + 8) * UVP + col];
                    a[mt][0] = __float_as_uint(to_tf32(fmaxf(u0.x + v0.x + bb.x, 0.f)));
                    a[mt][2] = __float_as_uint(to_tf32(fmaxf(u0.y + v0.y + bb.y, 0.f)));
                    a[mt][1] = __float_as_uint(to_tf32(fmaxf(u1.x + v1.x + bb.x, 0.f)));
                    a[mt][3] = __float_as_uint(to_tf32(fmaxf(u1.y + v1.y + bb.y, 0.f)));
                }
                #pragma unroll
                for (int j = 0; j < 4; j++) {
                    float2 bf = *(const float2*)&W2S[(n0 + 8 * j + rr) * W2P + col];
                    uint32_t bu0 = __float_as_uint(bf.x);
                    uint32_t bu1 = __float_as_uint(bf.y);
                    #pragma unroll
                    for (int mt = 0; mt < 2; mt++)
                        mma_tf32(acc[mt][j], a[mt][0], a[mt][1], a[mt][2], a[mt][3], bu0, bu1);
                }
            }

            // ---- scatter ----
            #pragma unroll
            for (int mt = 0; mt < 2; mt++) {
                #pragma unroll
                for (int half = 0; half < 2; half++) {
                    int er = er0 + 16 * mt + rr + 8 * half;
                    if (ebase + er < E) {
                        int node = sn[er];
                        float* base = out + (size_t)node * Dk;
                        #pragma unroll
                        for (int j = 0; j < 4; j++) {
                            int nb = n0 + 8 * j + 2 * q;
                            float cx = acc[mt][j][2 * half + 0] + b2r[j].x;
                            float cy = acc[mt][j][2 * half + 1] + b2r[j].y;
                            red_add_v2(base + nb, cx, cy);
                        }
                    }
                }
            }
            __syncthreads();   // US/VS free for next dir
        }
    }
}

extern "C" void kernel_launch(void* const* d_in, const int* in_sizes, int n_in,
                              void* d_out, int out_size) {
    const float* nodes = (const float*)d_in[0];
    const int*   edges = (const int*)d_in[1];
    const float* W1    = (const float*)d_in[2];
    const float* b1    = (const float*)d_in[3];
    const float* W2    = (const float*)d_in[4];
    const float* b2    = (const float*)d_in[5];
    float* out = (float*)d_out;

    int N = in_sizes[0] / Dk;
    int E = in_sizes[1] / 2;

    static int nsm = 0;
    const int uv_smem = (64 * UVPc + 128 * 128) * 4;
    if (!nsm) {
        cudaDeviceGetAttribute(&nsm, cudaDevAttrMultiProcessorCount, 0);
        cudaFuncSetAttribute(uv_kernel,   cudaFuncAttributeMaxDynamicSharedMemorySize, uv_smem);
        cudaFuncSetAttribute(edge_kernel, cudaFuncAttributeMaxDynamicSharedMemorySize, EDGE_SMEM_BYTES);
    }

    int n4 = (N * Dk) / 4;
    copy_kernel<<<(n4 + 255) / 256, 256>>>(nodes, out, n4);

    int uv_blocks = (N + 127) / 128;
    uv_kernel<<<uv_blocks, 256, uv_smem>>>(nodes, W1, N);

    int tiles = (E + TE - 1) / TE;
    edge_kernel<<<nsm, 256, EDGE_SMEM_BYTES>>>(edges, W2, b1, b2, out, E, tiles);
}